// round 6
// baseline (speedup 1.0000x reference)
#include <cuda_runtime.h>
#include <cstddef>

#define N_NODES 200000
#define N_EDGES 3200000
#define N_GRAPHS 64
#define HID 32
#define HEADS 4
#define SPAN 256          // contiguous edges per warp in k_edge (3.2M/256 = 12500 warps)

// ---------------- scratch (device globals; no allocation allowed) ----------------
__device__ float4 g_f4[(size_t)N_NODES * 8];     // f features: 8 float4 per node
__device__ float4 g_er4[N_NODES];                // er per node (4 heads)
__device__ float4 g_acc0[(size_t)N_NODES * 8];   // layer-0 unnormalized message sums
__device__ float4 g_den0[N_NODES];
__device__ float4 g_acc1[(size_t)N_NODES * 8];   // layer-1
__device__ float4 g_den1[N_NODES];
__device__ float g_sums[N_GRAPHS * HID];
__device__ float g_cnt[N_GRAPHS];
// CSR build (dst-sorted edge stream, shared by both layers)
__device__ int g_deg[N_NODES];
__device__ int g_cur[N_NODES];
__device__ int g_total;
__device__ int g_ss[N_EDGES];
__device__ int g_ds[N_EDGES];

__device__ __forceinline__ void red_add_v4(float* addr, float4 v) {
    asm volatile("red.global.add.v4.f32 [%0], {%1,%2,%3,%4};"
                 :: "l"(addr), "f"(v.x), "f"(v.y), "f"(v.z), "f"(v.w)
                 : "memory");
}

// exp via FMA-pipe polynomial (deg 7, |x|<=1: max rel err ~2.5e-5).
// e = leakyrelu(el+er) is O(0.05) for this model; __expf fallback for outliers.
__device__ __forceinline__ float fast_exp(float x) {
    if (fabsf(x) < 1.0f) {
        float p = 1.9841270e-4f;
        p = fmaf(p, x, 1.3888889e-3f);
        p = fmaf(p, x, 8.3333333e-3f);
        p = fmaf(p, x, 4.1666667e-2f);
        p = fmaf(p, x, 1.6666667e-1f);
        p = fmaf(p, x, 0.5f);
        p = fmaf(p, x, 1.0f);
        p = fmaf(p, x, 1.0f);
        return p;
    }
    return __expf(x);
}

// ---------------- K0: h = emb[node_ids]; f = h@W0; er; zero acc0/den0/deg ----------------
__global__ void __launch_bounds__(128) k_gather_fc(
        const int* __restrict__ node_ids,
        const float* __restrict__ emb,
        const float* __restrict__ W,
        const float* __restrict__ ar) {
    __shared__ float sW[HID * HID];
    __shared__ float sar[HID];
    int tid = threadIdx.x;
    for (int i = tid; i < HID * HID; i += blockDim.x) sW[i] = W[i];
    if (tid < HID) sar[tid] = ar[tid];
    __syncthreads();

    int n = blockIdx.x * blockDim.x + tid;
    if (n == 0) g_total = 0;
    if (n >= N_NODES) return;
    g_deg[n] = 0;

    int nid = __ldg(node_ids + n);
    const float4* hrow = (const float4*)(emb + (size_t)nid * HID);
    float h[HID];
#pragma unroll
    for (int i = 0; i < 8; i++) {
        float4 v = __ldg(hrow + i);
        h[4 * i] = v.x; h[4 * i + 1] = v.y; h[4 * i + 2] = v.z; h[4 * i + 3] = v.w;
    }
    float f[HID];
#pragma unroll
    for (int j = 0; j < HID; j++) f[j] = 0.f;
#pragma unroll
    for (int k = 0; k < HID; k++) {
        float hk = h[k];
        const float4* wr = (const float4*)(sW + k * HID);
#pragma unroll
        for (int j = 0; j < 8; j++) {
            float4 w = wr[j];
            f[4 * j]     += hk * w.x;
            f[4 * j + 1] += hk * w.y;
            f[4 * j + 2] += hk * w.z;
            f[4 * j + 3] += hk * w.w;
        }
    }
    const float4 z4 = make_float4(0.f, 0.f, 0.f, 0.f);
#pragma unroll
    for (int j = 0; j < 8; j++) {
        g_f4[n * 8 + j] = make_float4(f[4 * j], f[4 * j + 1], f[4 * j + 2], f[4 * j + 3]);
        g_acc0[n * 8 + j] = z4;
    }
    g_den0[n] = z4;

    float er[HEADS];
#pragma unroll
    for (int hh = 0; hh < HEADS; hh++) {
        float b = 0.f;
#pragma unroll
        for (int d = 0; d < 8; d++) b += f[hh * 8 + d] * sar[hh * 8 + d];
        er[hh] = b;
    }
    g_er4[n] = make_float4(er[0], er[1], er[2], er[3]);
}

// ---------------- CSR build: count -> assign ranges -> scatter ----------------
__global__ void k_count(const int* __restrict__ dst) {
    int e = blockIdx.x * blockDim.x + threadIdx.x;
    if (e < N_EDGES) atomicAdd(&g_deg[__ldg(dst + e)], 1);
}

// Warp-aggregated range assignment: one global atomic per warp; within-warp
// exclusive scan distributes starts. Block/warp ordering is arbitrary but
// ranges are disjoint and edges of one dst stay contiguous -> that is all
// k_edge needs.
__global__ void k_assign() {
    int n = blockIdx.x * blockDim.x + threadIdx.x;
    int lane = threadIdx.x & 31;
    int c = (n < N_NODES) ? g_deg[n] : 0;
    int v = c;
#pragma unroll
    for (int o = 1; o < 32; o <<= 1) {
        int t = __shfl_up_sync(0xffffffffu, v, o);
        if (lane >= o) v += t;
    }
    int wtotal = __shfl_sync(0xffffffffu, v, 31);
    int base = 0;
    if (lane == 31) base = atomicAdd(&g_total, wtotal);
    base = __shfl_sync(0xffffffffu, base, 31);
    if (n < N_NODES) g_cur[n] = base + (v - c);
}

__global__ void k_scatter(const int* __restrict__ src, const int* __restrict__ dst) {
    int e = blockIdx.x * blockDim.x + threadIdx.x;
    if (e >= N_EDGES) return;
    int d = __ldg(dst + e);
    int pos = atomicAdd(&g_cur[d], 1);
    g_ss[pos] = __ldg(src + e);
    g_ds[pos] = d;
}

// ---------------- K-edge: dst-sorted stream, run-accumulated REDs ----------------
// Warp owns SPAN contiguous sorted edges. 8-lane group per edge (sub = float4
// slot, head = sub>>1). Per edge: 1 random f-row wavefront; acc/den REDs only
// on dst-run breaks (avg every ~4 edges per group). All shuffles are computed
// unconditionally (warp-converged); only the REDs are predicated.
// Softmax max-pass elided (shift-invariant; |e|=O(0.05)) — validated r1-r5.
__global__ void __launch_bounds__(256, 6) k_edge(
        const float* __restrict__ al,
        float* __restrict__ acc, float* __restrict__ den) {
    int lane = threadIdx.x & 31;
    int warp = (blockIdx.x * blockDim.x + threadIdx.x) >> 5;
    int e0 = warp * SPAN;
    if (e0 >= N_EDGES) return;
    int sub = lane & 7;                 // float4 slot within 32-float row
    int head = sub >> 1;                // head of this slot
    int grp = lane >> 3;                // 8-lane group id (0..3)
    int gbase = lane & ~7;
    float4 sal = __ldg(((const float4*)al) + sub);

    int d_run = -1;
    float4 a_run = make_float4(0.f, 0.f, 0.f, 0.f);
    float den_l = 0.f;

    for (int c = 0; c < SPAN; c += 32) {
        int e = e0 + c + lane;
        int s = __ldg(g_ss + e);
        int d = __ldg(g_ds + e);
        float4 erv = __ldg(g_er4 + d);       // sorted dst -> few lines per warp

#pragma unroll
        for (int r = 0; r < 8; r++) {
            int idx = r * 4 + grp;
            int s_r = __shfl_sync(0xffffffffu, s, idx);
            int d_r = __shfl_sync(0xffffffffu, d, idx);
            float e0h = __shfl_sync(0xffffffffu, erv.x, idx);
            float e1h = __shfl_sync(0xffffffffu, erv.y, idx);
            float e2h = __shfl_sync(0xffffffffu, erv.z, idx);
            float e3h = __shfl_sync(0xffffffffu, erv.w, idx);
            float er_h = head == 0 ? e0h : head == 1 ? e1h : head == 2 ? e2h : e3h;

            float4 fv = __ldg((const float4*)g_f4 + s_r * 8 + sub);
            float part = fv.x * sal.x + fv.y * sal.y + fv.z * sal.z + fv.w * sal.w;
            float el_h = part + __shfl_xor_sync(0xffffffffu, part, 1);

            float x = el_h + er_h;
            x = x > 0.f ? x : 0.2f * x;      // leaky_relu(0.2)
            float ex = fast_exp(x);

            // den components of the CURRENT run (pre-update), warp-converged shuffles
            float y1 = __shfl_sync(0xffffffffu, den_l, gbase | 2);
            float y2 = __shfl_sync(0xffffffffu, den_l, gbase | 4);
            float y3 = __shfl_sync(0xffffffffu, den_l, gbase | 6);

            bool brk = (d_r != d_run);
            if (brk && d_run >= 0) {
                red_add_v4(acc + d_run * 32 + sub * 4, a_run);
                if (sub == 0)
                    red_add_v4(den + d_run * 4, make_float4(den_l, y1, y2, y3));
            }
            if (brk) {
                a_run = make_float4(0.f, 0.f, 0.f, 0.f);
                den_l = 0.f;
                d_run = d_r;
            }
            a_run.x = fmaf(ex, fv.x, a_run.x);
            a_run.y = fmaf(ex, fv.y, a_run.y);
            a_run.z = fmaf(ex, fv.z, a_run.z);
            a_run.w = fmaf(ex, fv.w, a_run.w);
            den_l += ex;
        }
    }
    // final flush (d_run is valid: SPAN >= 1 edge per group)
    float y1 = __shfl_sync(0xffffffffu, den_l, gbase | 2);
    float y2 = __shfl_sync(0xffffffffu, den_l, gbase | 4);
    float y3 = __shfl_sync(0xffffffffu, den_l, gbase | 6);
    red_add_v4(acc + d_run * 32 + sub * 4, a_run);
    if (sub == 0) red_add_v4(den + d_run * 4, make_float4(den_l, y1, y2, y3));
}

// ---------------- K2: normalize+bias+relu -> h1; f1 = h1@W1; er1; zero acc1/den1/sums ----------------
__global__ void __launch_bounds__(128) k_node_mid(
        const float* __restrict__ b0,
        const float* __restrict__ W,
        const float* __restrict__ ar) {
    __shared__ float sW[HID * HID];
    __shared__ float sar[HID], sb[HID];
    int tid = threadIdx.x;
    for (int i = tid; i < HID * HID; i += blockDim.x) sW[i] = W[i];
    if (tid < HID) { sar[tid] = ar[tid]; sb[tid] = b0[tid]; }
    __syncthreads();

    int n = blockIdx.x * blockDim.x + tid;
    if (n < N_GRAPHS * HID) g_sums[n] = 0.f;
    if (n < N_GRAPHS) g_cnt[n] = 0.f;
    if (n >= N_NODES) return;

    float4 dv4 = g_den0[n];
    float inv[HEADS];
    inv[0] = dv4.x > 0.f ? __fdividef(1.f, dv4.x) : 0.f;
    inv[1] = dv4.y > 0.f ? __fdividef(1.f, dv4.y) : 0.f;
    inv[2] = dv4.z > 0.f ? __fdividef(1.f, dv4.z) : 0.f;
    inv[3] = dv4.w > 0.f ? __fdividef(1.f, dv4.w) : 0.f;

    float h[HID];
#pragma unroll
    for (int j4 = 0; j4 < 8; j4++) {
        float4 v = g_acc0[n * 8 + j4];
        int hh = j4 >> 1;
        h[4 * j4]     = fmaxf(v.x * inv[hh] + sb[4 * j4],     0.f);
        h[4 * j4 + 1] = fmaxf(v.y * inv[hh] + sb[4 * j4 + 1], 0.f);
        h[4 * j4 + 2] = fmaxf(v.z * inv[hh] + sb[4 * j4 + 2], 0.f);
        h[4 * j4 + 3] = fmaxf(v.w * inv[hh] + sb[4 * j4 + 3], 0.f);
    }

    float f[HID];
#pragma unroll
    for (int j = 0; j < HID; j++) f[j] = 0.f;
#pragma unroll
    for (int k = 0; k < HID; k++) {
        float hk = h[k];
        const float4* wr = (const float4*)(sW + k * HID);
#pragma unroll
        for (int j = 0; j < 8; j++) {
            float4 w = wr[j];
            f[4 * j]     += hk * w.x;
            f[4 * j + 1] += hk * w.y;
            f[4 * j + 2] += hk * w.z;
            f[4 * j + 3] += hk * w.w;
        }
    }
    const float4 z4 = make_float4(0.f, 0.f, 0.f, 0.f);
#pragma unroll
    for (int j = 0; j < 8; j++) {
        g_f4[n * 8 + j] = make_float4(f[4 * j], f[4 * j + 1], f[4 * j + 2], f[4 * j + 3]);
        g_acc1[n * 8 + j] = z4;
    }
    g_den1[n] = z4;

    float er[HEADS];
#pragma unroll
    for (int hh = 0; hh < HEADS; hh++) {
        float b = 0.f;
#pragma unroll
        for (int d = 0; d < 8; d++) b += f[hh * 8 + d] * sar[hh * 8 + d];
        er[hh] = b;
    }
    g_er4[n] = make_float4(er[0], er[1], er[2], er[3]);
}

// ---------------- K4: h2 + run-length pooled per-graph sums (graph_ids sorted) ----------------
__global__ void k_pool(const int* __restrict__ graph_ids,
                       const float* __restrict__ b1) {
    int lane = threadIdx.x & 31;
    int warp = (blockIdx.x * blockDim.x + threadIdx.x) >> 5;
    int nwarp = (gridDim.x * blockDim.x) >> 5;
    int head = lane >> 3;
    float bl = __ldg(b1 + lane);
    const float* den1 = (const float*)g_den1;
    const float* acc1 = (const float*)g_acc1;
    int nchunk = (N_NODES + 31) / 32;
    for (int c = warp; c < nchunk; c += nwarp) {
        int base = c * 32;
        int lim = min(32, N_NODES - base);
        float runsum = 0.f;
        int rung = __ldg(graph_ids + base);
        int runcnt = 0;
        for (int i = 0; i < lim; i++) {
            int n = base + i;
            int gid = __ldg(graph_ids + n);
            float dv = __ldg(den1 + n * HEADS + head);
            float v  = __ldg(acc1 + (size_t)n * HID + lane);
            float hv = dv > 0.f ? __fdividef(v, dv) : 0.f;
            hv = fmaxf(hv + bl, 0.f);
            if (gid != rung) {
                atomicAdd(g_sums + rung * HID + lane, runsum);
                if (lane == 0) atomicAdd(g_cnt + rung, (float)runcnt);
                runsum = 0.f; runcnt = 0; rung = gid;
            }
            runsum += hv; runcnt++;
        }
        atomicAdd(g_sums + rung * HID + lane, runsum);
        if (lane == 0) atomicAdd(g_cnt + rung, (float)runcnt);
    }
}

// ---------------- K5: scorer MLP ----------------
__global__ void k_score(const float* __restrict__ sw1, const float* __restrict__ sb1,
                        const float* __restrict__ sw2, const float* __restrict__ sb2,
                        float* __restrict__ out) {
    __shared__ float s1[HID * HID];
    __shared__ float sb[HID], s2[HID];
    int t = threadIdx.x;
    for (int i = t; i < HID * HID; i += blockDim.x) s1[i] = sw1[i];
    if (t < HID) { sb[t] = sb1[t]; s2[t] = sw2[t]; }
    __syncthreads();
    if (t < N_GRAPHS) {
        float c = fmaxf(g_cnt[t], 1.f);
        float invc = __fdividef(1.f, c);
        float hg[HID];
#pragma unroll
        for (int k = 0; k < HID; k++) hg[k] = g_sums[t * HID + k] * invc;
        float score = __ldg(sb2);
#pragma unroll
        for (int j = 0; j < HID; j++) {
            float a = sb[j];
#pragma unroll
            for (int k = 0; k < HID; k++) a += hg[k] * s1[k * HID + j];
            a = fmaxf(a, 0.f);
            score += a * s2[j];
        }
        out[t] = score;
    }
}

// ---------------- launch ----------------
extern "C" void kernel_launch(void* const* d_in, const int* in_sizes, int n_in,
                              void* d_out, int out_size) {
    const int*   node_ids = (const int*)d_in[0];
    const int*   src      = (const int*)d_in[1];
    const int*   dst      = (const int*)d_in[2];
    const int*   gids     = (const int*)d_in[3];
    const float* emb      = (const float*)d_in[4];
    const float* W0       = (const float*)d_in[5];
    const float* al0      = (const float*)d_in[6];
    const float* ar0      = (const float*)d_in[7];
    const float* b0       = (const float*)d_in[8];
    const float* W1       = (const float*)d_in[9];
    const float* al1      = (const float*)d_in[10];
    const float* ar1      = (const float*)d_in[11];
    const float* b1       = (const float*)d_in[12];
    const float* sw1      = (const float*)d_in[13];
    const float* sb1      = (const float*)d_in[14];
    const float* sw2      = (const float*)d_in[15];
    const float* sb2      = (const float*)d_in[16];
    float* out = (float*)d_out;

    void *acc0, *den0, *acc1, *den1;
    cudaGetSymbolAddress(&acc0, g_acc0);
    cudaGetSymbolAddress(&den0, g_den0);
    cudaGetSymbolAddress(&acc1, g_acc1);
    cudaGetSymbolAddress(&den1, g_den1);

    const int nodeBlocks128 = (N_NODES + 127) / 128;
    const int edgeBlocks = (N_EDGES + 255) / 256;
    const int warps = N_EDGES / SPAN;                  // 12500
    const int edgeKBlocks = (warps + 7) / 8;           // 8 warps per 256-thr block

    k_gather_fc<<<nodeBlocks128, 128>>>(node_ids, emb, W0, ar0);
    k_count<<<edgeBlocks, 256>>>(dst);
    k_assign<<<(N_NODES + 255) / 256, 256>>>();
    k_scatter<<<edgeBlocks, 256>>>(src, dst);
    k_edge<<<edgeKBlocks, 256>>>(al0, (float*)acc0, (float*)den0);
    k_node_mid<<<nodeBlocks128, 128>>>(b0, W1, ar1);
    k_edge<<<edgeKBlocks, 256>>>(al1, (float*)acc1, (float*)den1);
    k_pool<<<(6250 + 7) / 8, 256>>>(gids, b1);
    k_score<<<1, 64>>>(sw1, sb1, sw2, sb2, out);
}

// round 7
// speedup vs baseline: 1.0466x; 1.0466x over previous
#include <cuda_runtime.h>
#include <cstddef>

#define N_NODES 200000
#define N_EDGES 3200000
#define N_GRAPHS 64
#define HID 32
#define HEADS 4
#define SPAN 256           // edges per warp in k_edge; 64 contiguous per 8-lane group
#define NWARPS (N_EDGES / SPAN)   // 12500

// ---------------- scratch (device globals; no allocation allowed) ----------------
__device__ float g_f[(size_t)N_NODES * HID];
__device__ float g_er[(size_t)N_NODES * HEADS];
__device__ float g_acc0[(size_t)N_NODES * HID];
__device__ float g_den0[(size_t)N_NODES * 8];    // per-head den, duplicated x2 (slot = sub)
__device__ float g_acc1[(size_t)N_NODES * HID];
__device__ float g_den1[(size_t)N_NODES * 8];
__device__ float g_sums[N_GRAPHS * HID];
__device__ float g_cnt[N_GRAPHS];
// CSR build (dst-sorted edge stream, built once, used by both layers)
__device__ int  g_deg[N_NODES];
__device__ int  g_cur[N_NODES];
__device__ int  g_total;
__device__ int2 g_es[N_EDGES];                   // {src, dst} sorted by dst

__device__ __forceinline__ void red_add_v4(float* addr, float4 v) {
    asm volatile("red.global.add.v4.f32 [%0], {%1,%2,%3,%4};"
                 :: "l"(addr), "f"(v.x), "f"(v.y), "f"(v.z), "f"(v.w)
                 : "memory");
}
__device__ __forceinline__ void red_add_f(float* addr, float v) {
    asm volatile("red.global.add.f32 [%0], %1;" :: "l"(addr), "f"(v) : "memory");
}

// ---------------- K0: warp-per-node: h = emb[node_ids]; f = h@W0; er; zero acc0/den0/deg ----------------
__global__ void __launch_bounds__(256) k_gather_fc(
        const int* __restrict__ node_ids,
        const float* __restrict__ emb,
        const float* __restrict__ W,
        const float* __restrict__ ar) {
    __shared__ float sW[HID * HID];
    int tid = threadIdx.x;
    int t = blockIdx.x * 256 + tid;
    for (int i = tid; i < HID * HID; i += 256) sW[i] = W[i];
    if (t < N_NODES) g_deg[t] = 0;
    if (t == 0) g_total = 0;
    __syncthreads();

    int n = t >> 5;                       // warp per node
    int lane = tid & 31;
    if (n >= N_NODES) return;

    int nid = __ldg(node_ids + n);
    float h = __ldg(emb + (size_t)nid * HID + lane);     // coalesced 128B row
    float f = 0.f;
#pragma unroll
    for (int k = 0; k < HID; k++)
        f = fmaf(__shfl_sync(0xffffffffu, h, k), sW[k * HID + lane], f);

    g_f[(size_t)n * HID + lane] = f;
    g_acc0[(size_t)n * HID + lane] = 0.f;
    if (lane < 8) g_den0[(size_t)n * 8 + lane] = 0.f;

    // er[head]: segmented reduce of f*ar over 8-lane groups
    float p = f * __ldg(ar + lane);
    p += __shfl_xor_sync(0xffffffffu, p, 1);
    p += __shfl_xor_sync(0xffffffffu, p, 2);
    p += __shfl_xor_sync(0xffffffffu, p, 4);
    if ((lane & 7) == 0) g_er[n * HEADS + (lane >> 3)] = p;
}

// ---------------- CSR build: count -> assign -> scatter (int2 combined) ----------------
__global__ void k_count(const int* __restrict__ dst) {
    int e = blockIdx.x * blockDim.x + threadIdx.x;
    if (e < N_EDGES) atomicAdd(&g_deg[__ldg(dst + e)], 1);
}

__global__ void k_assign() {
    int n = blockIdx.x * blockDim.x + threadIdx.x;
    int lane = threadIdx.x & 31;
    int c = (n < N_NODES) ? g_deg[n] : 0;
    int v = c;
#pragma unroll
    for (int o = 1; o < 32; o <<= 1) {
        int tv = __shfl_up_sync(0xffffffffu, v, o);
        if (lane >= o) v += tv;
    }
    int wtotal = __shfl_sync(0xffffffffu, v, 31);
    int base = 0;
    if (lane == 31) base = atomicAdd(&g_total, wtotal);
    base = __shfl_sync(0xffffffffu, base, 31);
    if (n < N_NODES) g_cur[n] = base + (v - c);
}

__global__ void k_scatter(const int* __restrict__ src, const int* __restrict__ dst) {
    int e = blockIdx.x * blockDim.x + threadIdx.x;
    if (e >= N_EDGES) return;
    int s = __ldg(src + e);
    int d = __ldg(dst + e);
    int pos = atomicAdd(&g_cur[d], 1);
    g_es[pos] = make_int2(s, d);          // single 8B store
}

// ---------------- K-edge: sorted stream, contiguous 64 edges per 8-lane group ----------------
// Per edge: 1 random f-row wavefront. er loaded only on run break (~1/16 edges);
// acc flush = red.v4, den flush = per-lane scalar red (no shuffles), both
// predicated on break. Softmax max-pass elided (shift-invariant; |e|=O(0.05)).
__global__ void __launch_bounds__(256) k_edge(
        const float* __restrict__ al,
        float* __restrict__ acc, float* __restrict__ den) {
    int lane = threadIdx.x & 31;
    int warp = (blockIdx.x * blockDim.x + threadIdx.x) >> 5;
    if (warp >= NWARPS) return;
    int sub = lane & 7;
    int grp = lane >> 3;
    int head = sub >> 1;
    int gbase = grp << 3;
    int gstart = warp * SPAN + grp * 64;          // group's contiguous 64-edge span
    float4 sal = __ldg(((const float4*)al) + sub);

    int d_run = -1;
    float er_h = 0.f, den_l = 0.f;
    float4 a_run = make_float4(0.f, 0.f, 0.f, 0.f);

    for (int o = 0; o < 64; o += 8) {
        int2 ed = __ldg(g_es + gstart + o + sub);  // 8 edges preloaded per group
#pragma unroll
        for (int i = 0; i < 8; i++) {
            int s_r = __shfl_sync(0xffffffffu, ed.x, gbase + i);
            int d_r = __shfl_sync(0xffffffffu, ed.y, gbase + i);
            if (d_r != d_run) {
                if (d_run >= 0) {
                    red_add_v4(acc + d_run * 32 + sub * 4, a_run);
                    red_add_f(den + d_run * 8 + sub, den_l);
                }
                d_run = d_r;
                a_run = make_float4(0.f, 0.f, 0.f, 0.f);
                den_l = 0.f;
                er_h = __ldg(g_er + d_r * HEADS + head);
            }
            float4 fv = __ldg((const float4*)(g_f + (size_t)s_r * HID) + sub);
            float part = fv.x * sal.x + fv.y * sal.y + fv.z * sal.z + fv.w * sal.w;
            float el = part + __shfl_xor_sync(0xffffffffu, part, 1);
            float x = el + er_h;
            x = x > 0.f ? x : 0.2f * x;           // leaky_relu(0.2)
            float ex = __expf(x);
            a_run.x = fmaf(ex, fv.x, a_run.x);
            a_run.y = fmaf(ex, fv.y, a_run.y);
            a_run.z = fmaf(ex, fv.z, a_run.z);
            a_run.w = fmaf(ex, fv.w, a_run.w);
            den_l += ex;
        }
    }
    red_add_v4(acc + d_run * 32 + sub * 4, a_run);
    red_add_f(den + d_run * 8 + sub, den_l);
}

// ---------------- K2: warp-per-node: h1 = relu(acc0/den0 + b0); f1 = h1@W1; er1; zero acc1/den1/sums ----------------
__global__ void __launch_bounds__(256) k_node_mid(
        const float* __restrict__ b0,
        const float* __restrict__ W,
        const float* __restrict__ ar) {
    __shared__ float sW[HID * HID];
    int tid = threadIdx.x;
    int t = blockIdx.x * 256 + tid;
    for (int i = tid; i < HID * HID; i += 256) sW[i] = W[i];
    if (t < N_GRAPHS * HID) g_sums[t] = 0.f;
    if (t < N_GRAPHS) g_cnt[t] = 0.f;
    __syncthreads();

    int n = t >> 5;
    int lane = tid & 31;
    if (n >= N_NODES) return;

    float dv = g_den0[(size_t)n * 8 + ((lane >> 3) << 1)];
    float inv = dv > 0.f ? __fdividef(1.f, dv) : 0.f;
    float a = g_acc0[(size_t)n * HID + lane];
    float h = fmaxf(fmaf(a, inv, __ldg(b0 + lane)), 0.f);

    float f = 0.f;
#pragma unroll
    for (int k = 0; k < HID; k++)
        f = fmaf(__shfl_sync(0xffffffffu, h, k), sW[k * HID + lane], f);

    g_f[(size_t)n * HID + lane] = f;
    g_acc1[(size_t)n * HID + lane] = 0.f;
    if (lane < 8) g_den1[(size_t)n * 8 + lane] = 0.f;

    float p = f * __ldg(ar + lane);
    p += __shfl_xor_sync(0xffffffffu, p, 1);
    p += __shfl_xor_sync(0xffffffffu, p, 2);
    p += __shfl_xor_sync(0xffffffffu, p, 4);
    if ((lane & 7) == 0) g_er[n * HEADS + (lane >> 3)] = p;
}

// ---------------- K4: h2 + run-length pooled per-graph sums (graph_ids sorted) ----------------
__global__ void k_pool(const int* __restrict__ graph_ids,
                       const float* __restrict__ b1) {
    int lane = threadIdx.x & 31;
    int warp = (blockIdx.x * blockDim.x + threadIdx.x) >> 5;
    int nwarp = (gridDim.x * blockDim.x) >> 5;
    int dslot = (lane >> 3) << 1;
    float bl = __ldg(b1 + lane);
    int nchunk = (N_NODES + 31) / 32;
    for (int c = warp; c < nchunk; c += nwarp) {
        int base = c * 32;
        int lim = min(32, N_NODES - base);
        float runsum = 0.f;
        int rung = __ldg(graph_ids + base);
        int runcnt = 0;
        for (int i = 0; i < lim; i++) {
            int n = base + i;
            int gid = __ldg(graph_ids + n);            // uniform across warp
            float dv = g_den1[(size_t)n * 8 + dslot];
            float v  = g_acc1[(size_t)n * HID + lane];
            float hv = dv > 0.f ? __fdividef(v, dv) : 0.f;
            hv = fmaxf(hv + bl, 0.f);
            if (gid != rung) {
                atomicAdd(g_sums + rung * HID + lane, runsum);
                if (lane == 0) atomicAdd(g_cnt + rung, (float)runcnt);
                runsum = 0.f; runcnt = 0; rung = gid;
            }
            runsum += hv; runcnt++;
        }
        atomicAdd(g_sums + rung * HID + lane, runsum);
        if (lane == 0) atomicAdd(g_cnt + rung, (float)runcnt);
    }
}

// ---------------- K5: scorer MLP ----------------
__global__ void k_score(const float* __restrict__ sw1, const float* __restrict__ sb1,
                        const float* __restrict__ sw2, const float* __restrict__ sb2,
                        float* __restrict__ out) {
    __shared__ float s1[HID * HID];
    __shared__ float sb[HID], s2[HID];
    int t = threadIdx.x;
    for (int i = t; i < HID * HID; i += blockDim.x) s1[i] = sw1[i];
    if (t < HID) { sb[t] = sb1[t]; s2[t] = sw2[t]; }
    __syncthreads();
    if (t < N_GRAPHS) {
        float c = fmaxf(g_cnt[t], 1.f);
        float invc = __fdividef(1.f, c);
        float hg[HID];
#pragma unroll
        for (int k = 0; k < HID; k++) hg[k] = g_sums[t * HID + k] * invc;
        float score = __ldg(sb2);
#pragma unroll
        for (int j = 0; j < HID; j++) {
            float a = sb[j];
#pragma unroll
            for (int k = 0; k < HID; k++) a += hg[k] * s1[k * HID + j];
            a = fmaxf(a, 0.f);
            score += a * s2[j];
        }
        out[t] = score;
    }
}

// ---------------- launch ----------------
extern "C" void kernel_launch(void* const* d_in, const int* in_sizes, int n_in,
                              void* d_out, int out_size) {
    const int*   node_ids = (const int*)d_in[0];
    const int*   src      = (const int*)d_in[1];
    const int*   dst      = (const int*)d_in[2];
    const int*   gids     = (const int*)d_in[3];
    const float* emb      = (const float*)d_in[4];
    const float* W0       = (const float*)d_in[5];
    const float* al0      = (const float*)d_in[6];
    const float* ar0      = (const float*)d_in[7];
    const float* b0       = (const float*)d_in[8];
    const float* W1       = (const float*)d_in[9];
    const float* al1      = (const float*)d_in[10];
    const float* ar1      = (const float*)d_in[11];
    const float* b1       = (const float*)d_in[12];
    const float* sw1      = (const float*)d_in[13];
    const float* sb1      = (const float*)d_in[14];
    const float* sw2      = (const float*)d_in[15];
    const float* sb2      = (const float*)d_in[16];
    float* out = (float*)d_out;

    void *acc0, *den0, *acc1, *den1;
    cudaGetSymbolAddress(&acc0, g_acc0);
    cudaGetSymbolAddress(&den0, g_den0);
    cudaGetSymbolAddress(&acc1, g_acc1);
    cudaGetSymbolAddress(&den1, g_den1);

    const int nodeWarpBlocks = (N_NODES * 32 + 255) / 256;   // warp per node
    const int edgeBlocks = (N_EDGES + 255) / 256;
    const int edgeKBlocks = (NWARPS + 7) / 8;

    k_gather_fc<<<nodeWarpBlocks, 256>>>(node_ids, emb, W0, ar0);
    k_count<<<edgeBlocks, 256>>>(dst);
    k_assign<<<(N_NODES + 255) / 256, 256>>>();
    k_scatter<<<edgeBlocks, 256>>>(src, dst);
    k_edge<<<edgeKBlocks, 256>>>(al0, (float*)acc0, (float*)den0);
    k_node_mid<<<nodeWarpBlocks, 256>>>(b0, W1, ar1);
    k_edge<<<edgeKBlocks, 256>>>(al1, (float*)acc1, (float*)den1);
    k_pool<<<(6250 + 7) / 8, 256>>>(gids, b1);
    k_score<<<1, 64>>>(sw1, sb1, sw2, sb2, out);
}